// round 1
// baseline (speedup 1.0000x reference)
#include <cuda_runtime.h>
#include <math.h>

// Problem constants
#define BB   4
#define SS   2048
#define DM   512
#define DF   2048
#define ROWS (BB*SS)   // 8192

// GEMM tiling
#define TBM 64
#define TBN 64
#define TBK 16

// ---------------- scratch (device globals; no runtime alloc allowed) ----------------
__device__ float g_Q[ROWS*DM];
__device__ float g_K[ROWS*DM];
__device__ float g_V[ROWS*DM];
__device__ float g_Sc[(size_t)BB*SS*SS];   // attention scores / probs  (64 MB)
__device__ float g_attn[ROWS*DM];
__device__ float g_h[ROWS*DM];
__device__ float g_f[ROWS*DF];             // FFN hidden (64 MB)
__device__ float g_f2[ROWS*DM];

// ---------------- block reductions (broadcast result to all threads) ----------------
__device__ __forceinline__ float blockAllReduceSum(float v) {
    __shared__ float sh[33];
    #pragma unroll
    for (int o = 16; o; o >>= 1) v += __shfl_xor_sync(0xffffffffu, v, o);
    int w = threadIdx.x >> 5;
    if ((threadIdx.x & 31) == 0) sh[w] = v;
    __syncthreads();
    if (threadIdx.x == 0) {
        float t = 0.f;
        int nw = blockDim.x >> 5;
        for (int i = 0; i < nw; i++) t += sh[i];
        sh[32] = t;
    }
    __syncthreads();
    float r = sh[32];
    __syncthreads();
    return r;
}

__device__ __forceinline__ float blockAllReduceMax(float v) {
    __shared__ float sh[33];
    #pragma unroll
    for (int o = 16; o; o >>= 1) v = fmaxf(v, __shfl_xor_sync(0xffffffffu, v, o));
    int w = threadIdx.x >> 5;
    if ((threadIdx.x & 31) == 0) sh[w] = v;
    __syncthreads();
    if (threadIdx.x == 0) {
        float t = -3.4e38f;
        int nw = blockDim.x >> 5;
        for (int i = 0; i < nw; i++) t = fmaxf(t, sh[i]);
        sh[32] = t;
    }
    __syncthreads();
    float r = sh[32];
    __syncthreads();
    return r;
}

// ---------------- GEMM NN: C = A[M,K] * B[K,N] (+bias)(+relu), batched ----------------
// All dims assumed multiples of the tile (true for every call site here).
template<int HASBIAS, int RELU>
__global__ void gemm_nn_kernel(const float* __restrict__ A, const float* __restrict__ Bm,
                               const float* __restrict__ bias, float* __restrict__ C,
                               int M, int N, int K,
                               size_t sA, size_t sB, size_t sC)
{
    __shared__ float As[TBK][TBM + 4];
    __shared__ float Bs[TBK][TBN + 4];

    const float* Ab = A  + (size_t)blockIdx.z * sA;
    const float* Bb = Bm + (size_t)blockIdx.z * sB;
    float*       Cb = C  + (size_t)blockIdx.z * sC;

    const int tx = threadIdx.x, ty = threadIdx.y;
    const int tid = ty * 16 + tx;
    const int m0 = blockIdx.y * TBM;
    const int n0 = blockIdx.x * TBN;

    float acc[4][4] = {};

    for (int k0 = 0; k0 < K; k0 += TBK) {
        #pragma unroll
        for (int i = 0; i < 4; i++) {
            int idx = tid + i * 256;
            int r = idx >> 4, c = idx & 15;              // A tile 64x16
            As[c][r] = Ab[(size_t)(m0 + r) * K + k0 + c];
        }
        #pragma unroll
        for (int i = 0; i < 4; i++) {
            int idx = tid + i * 256;
            int r = idx >> 6, c = idx & 63;              // B tile 16x64
            Bs[r][c] = Bb[(size_t)(k0 + r) * N + n0 + c];
        }
        __syncthreads();

        #pragma unroll
        for (int kk = 0; kk < TBK; kk++) {
            float4 a4 = *(const float4*)&As[kk][ty * 4];
            float4 b4 = *(const float4*)&Bs[kk][tx * 4];
            float av[4] = {a4.x, a4.y, a4.z, a4.w};
            float bv[4] = {b4.x, b4.y, b4.z, b4.w};
            #pragma unroll
            for (int i = 0; i < 4; i++)
                #pragma unroll
                for (int j = 0; j < 4; j++)
                    acc[i][j] += av[i] * bv[j];
        }
        __syncthreads();
    }

    #pragma unroll
    for (int i = 0; i < 4; i++) {
        int row = m0 + ty * 4 + i;
        #pragma unroll
        for (int j = 0; j < 4; j++) {
            int col = n0 + tx * 4 + j;
            float v = acc[i][j];
            if (HASBIAS) v += bias[col];
            if (RELU)    v = fmaxf(v, 0.f);
            Cb[(size_t)row * N + col] = v;
        }
    }
}

// ---------------- GEMM NT: C = alpha * A[M,K] * B[N,K]^T, batched (scores) ----------------
__global__ void gemm_nt_kernel(const float* __restrict__ A, const float* __restrict__ Bm,
                               float* __restrict__ C,
                               int M, int N, int K,
                               size_t sA, size_t sB, size_t sC, float alpha)
{
    __shared__ float As[TBK][TBM + 4];
    __shared__ float Bs[TBK][TBN + 4];

    const float* Ab = A  + (size_t)blockIdx.z * sA;
    const float* Bb = Bm + (size_t)blockIdx.z * sB;
    float*       Cb = C  + (size_t)blockIdx.z * sC;

    const int tx = threadIdx.x, ty = threadIdx.y;
    const int tid = ty * 16 + tx;
    const int m0 = blockIdx.y * TBM;
    const int n0 = blockIdx.x * TBN;

    float acc[4][4] = {};

    for (int k0 = 0; k0 < K; k0 += TBK) {
        #pragma unroll
        for (int i = 0; i < 4; i++) {
            int idx = tid + i * 256;
            int r = idx >> 4, c = idx & 15;
            As[c][r] = Ab[(size_t)(m0 + r) * K + k0 + c];
        }
        #pragma unroll
        for (int i = 0; i < 4; i++) {
            int idx = tid + i * 256;
            int n = idx >> 4, k = idx & 15;              // B tile: rows of B (N-dim) x K
            Bs[k][n] = Bb[(size_t)(n0 + n) * K + k0 + k];
        }
        __syncthreads();

        #pragma unroll
        for (int kk = 0; kk < TBK; kk++) {
            float4 a4 = *(const float4*)&As[kk][ty * 4];
            float4 b4 = *(const float4*)&Bs[kk][tx * 4];
            float av[4] = {a4.x, a4.y, a4.z, a4.w};
            float bv[4] = {b4.x, b4.y, b4.z, b4.w};
            #pragma unroll
            for (int i = 0; i < 4; i++)
                #pragma unroll
                for (int j = 0; j < 4; j++)
                    acc[i][j] += av[i] * bv[j];
        }
        __syncthreads();
    }

    #pragma unroll
    for (int i = 0; i < 4; i++) {
        int row = m0 + ty * 4 + i;
        #pragma unroll
        for (int j = 0; j < 4; j++) {
            int col = n0 + tx * 4 + j;
            Cb[(size_t)row * N + col] = acc[i][j] * alpha;
        }
    }
}

// ---------------- row softmax (in place), cols = 2048, 256 threads ----------------
__global__ void softmax_kernel(float* __restrict__ Sp, int cols)
{
    float* row = Sp + (size_t)blockIdx.x * cols;
    int tid = threadIdx.x;

    float m = -3.4e38f;
    for (int i = tid; i < cols; i += 256) m = fmaxf(m, row[i]);
    m = blockAllReduceMax(m);

    float s = 0.f;
    for (int i = tid; i < cols; i += 256) {
        float e = __expf(row[i] - m);
        row[i] = e;
        s += e;
    }
    s = blockAllReduceSum(s);
    float inv = 1.f / s;

    for (int i = tid; i < cols; i += 256) row[i] *= inv;
}

// ---------------- fused residual add + LayerNorm, D = 512, 256 threads ----------------
__global__ void add_ln_kernel(const float* __restrict__ a, const float* __restrict__ b,
                              const float* __restrict__ gamma, const float* __restrict__ beta,
                              float* __restrict__ out)
{
    const size_t row = blockIdx.x;
    const int tid = threadIdx.x;
    const float* ar = a + row * DM;
    const float* br = b + row * DM;

    float v0 = ar[tid]       + br[tid];
    float v1 = ar[tid + 256] + br[tid + 256];

    float s  = blockAllReduceSum(v0 + v1);
    float sq = blockAllReduceSum(v0 * v0 + v1 * v1);

    float mean = s * (1.f / DM);
    float var  = sq * (1.f / DM) - mean * mean;
    float inv  = rsqrtf(var + 1e-5f);

    float* o = out + row * DM;
    o[tid]       = (v0 - mean) * inv * gamma[tid]       + beta[tid];
    o[tid + 256] = (v1 - mean) * inv * gamma[tid + 256] + beta[tid + 256];
}

// ---------------- launch ----------------
extern "C" void kernel_launch(void* const* d_in, const int* in_sizes, int n_in,
                              void* d_out, int out_size)
{
    const float* q  = (const float*)d_in[0];
    const float* k  = (const float*)d_in[1];
    const float* v  = (const float*)d_in[2];
    const float* x  = (const float*)d_in[3];
    const float* Wq = (const float*)d_in[4];
    const float* bq = (const float*)d_in[5];
    const float* Wk = (const float*)d_in[6];
    const float* bk = (const float*)d_in[7];
    const float* Wv = (const float*)d_in[8];
    const float* bv = (const float*)d_in[9];
    const float* g1 = (const float*)d_in[10];
    const float* be1= (const float*)d_in[11];
    const float* W1 = (const float*)d_in[12];
    const float* b1 = (const float*)d_in[13];
    const float* W2 = (const float*)d_in[14];
    const float* b2 = (const float*)d_in[15];
    const float* g2 = (const float*)d_in[16];
    const float* be2= (const float*)d_in[17];
    float* out = (float*)d_out;

    float *pQ, *pK, *pV, *pS, *pAttn, *pH, *pF, *pF2;
    cudaGetSymbolAddress((void**)&pQ,    g_Q);
    cudaGetSymbolAddress((void**)&pK,    g_K);
    cudaGetSymbolAddress((void**)&pV,    g_V);
    cudaGetSymbolAddress((void**)&pS,    g_Sc);
    cudaGetSymbolAddress((void**)&pAttn, g_attn);
    cudaGetSymbolAddress((void**)&pH,    g_h);
    cudaGetSymbolAddress((void**)&pF,    g_f);
    cudaGetSymbolAddress((void**)&pF2,   g_f2);

    dim3 tb(16, 16);

    // 1) QKV projections: [8192,512] @ [512,512] + bias
    {
        dim3 grid(DM / TBN, ROWS / TBM, 1);
        gemm_nn_kernel<1, 0><<<grid, tb>>>(q, Wq, bq, pQ, ROWS, DM, DM, 0, 0, 0);
        gemm_nn_kernel<1, 0><<<grid, tb>>>(k, Wk, bk, pK, ROWS, DM, DM, 0, 0, 0);
        gemm_nn_kernel<1, 0><<<grid, tb>>>(v, Wv, bv, pV, ROWS, DM, DM, 0, 0, 0);
    }

    // 2) scores = Q @ K^T / sqrt(D), per batch
    {
        dim3 grid(SS / TBN, SS / TBM, BB);
        gemm_nt_kernel<<<grid, tb>>>(pQ, pK, pS, SS, SS, DM,
                                     (size_t)SS * DM, (size_t)SS * DM, (size_t)SS * SS,
                                     1.f / sqrtf((float)DM));
    }

    // 3) softmax over last dim
    softmax_kernel<<<BB * SS, 256>>>(pS, SS);

    // 4) attn = P @ V, per batch
    {
        dim3 grid(DM / TBN, SS / TBM, BB);
        gemm_nn_kernel<0, 0><<<grid, tb>>>(pS, pV, nullptr, pAttn, SS, DM, SS,
                                           (size_t)SS * SS, (size_t)SS * DM, (size_t)SS * DM);
    }

    // 5) h = LN(attn + x)
    add_ln_kernel<<<ROWS, 256>>>(pAttn, x, g1, be1, pH);

    // 6) f = relu(h @ W1 + b1): [8192,512] @ [512,2048]
    {
        dim3 grid(DF / TBN, ROWS / TBM, 1);
        gemm_nn_kernel<1, 1><<<grid, tb>>>(pH, W1, b1, pF, ROWS, DF, DM, 0, 0, 0);
    }

    // 7) f2 = f @ W2 + b2: [8192,2048] @ [2048,512]
    {
        dim3 grid(DM / TBN, ROWS / TBM, 1);
        gemm_nn_kernel<1, 0><<<grid, tb>>>(pF, W2, b2, pF2, ROWS, DM, DF, 0, 0, 0);
    }

    // 8) out = LN(f2 + h)
    add_ln_kernel<<<ROWS, 256>>>(pF2, pH, g2, be2, out);
}

// round 2
// speedup vs baseline: 3.5938x; 3.5938x over previous
#include <cuda_runtime.h>
#include <math.h>
#include <stdint.h>

// Problem constants
#define BB   4
#define SS   2048
#define DM   512
#define DF   2048
#define ROWS (BB*SS)   // 8192

// GEMM tiling (tensor core)
#define BM 128
#define BN 128
#define BK 16

// ---------------- scratch (device globals; no runtime alloc allowed) ----------------
__device__ float g_Q[ROWS*DM];
__device__ float g_K[ROWS*DM];
__device__ float g_KT[ROWS*DM];            // K transposed per batch: [B][D][S]
__device__ float g_V[ROWS*DM];
__device__ float g_Sc[(size_t)BB*SS*SS];   // attention scores / probs (64 MB)
__device__ float g_attn[ROWS*DM];
__device__ float g_h[ROWS*DM];
__device__ float g_f[ROWS*DF];             // FFN hidden (64 MB)
__device__ float g_f2[ROWS*DM];

// ---------------- helpers ----------------
__device__ __forceinline__ uint32_t smem_u32(const void* p) {
    return (uint32_t)__cvta_generic_to_shared(p);
}
__device__ __forceinline__ void cp_async16(void* dst, const void* src) {
    asm volatile("cp.async.cg.shared.global [%0], [%1], 16;"
                 :: "r"(smem_u32(dst)), "l"(src));
}
__device__ __forceinline__ void cp_commit() {
    asm volatile("cp.async.commit_group;");
}
__device__ __forceinline__ void cp_wait0() {
    asm volatile("cp.async.wait_group 0;");
}

__device__ __forceinline__ void mma_tf32(float c[4],
                                         uint32_t a0, uint32_t a1, uint32_t a2, uint32_t a3,
                                         uint32_t b0, uint32_t b1) {
    asm volatile(
        "mma.sync.aligned.m16n8k8.row.col.f32.tf32.tf32.f32 "
        "{%0,%1,%2,%3}, {%4,%5,%6,%7}, {%8,%9}, {%0,%1,%2,%3};"
        : "+f"(c[0]), "+f"(c[1]), "+f"(c[2]), "+f"(c[3])
        : "r"(a0), "r"(a1), "r"(a2), "r"(a3), "r"(b0), "r"(b1));
}

// ---------------- tensor-core GEMM NN: C = alpha*(A[M,K] @ B[K,N] + bias), relu opt ----------------
// A,B,C row-major; M%128==0, N%128==0, K%16==0. Batched via blockIdx.z + strides.
template<int HASBIAS, int RELU>
__global__ void __launch_bounds__(256, 2)
gemm_tc(const float* __restrict__ A, const float* __restrict__ B,
        const float* __restrict__ bias, float* __restrict__ C,
        int M, int N, int K, size_t sA, size_t sB, size_t sC, float alpha)
{
    __shared__ float As[2][BM][BK + 4];    // pad 4 -> conflict-free a-frag loads
    __shared__ float Bs[2][BK][BN + 8];    // pad 8 -> conflict-free b-frag loads

    const float* Ab = A + (size_t)blockIdx.z * sA;
    const float* Bb = B + (size_t)blockIdx.z * sB;
    float*       Cb = C + (size_t)blockIdx.z * sC;

    const int tid  = threadIdx.x;
    const int wid  = tid >> 5, lane = tid & 31;
    const int g    = lane >> 2, t4 = lane & 3;
    const int wm   = wid >> 2, wn = wid & 3;         // 2 x 4 warp grid
    const int m0   = blockIdx.y * BM;
    const int n0   = blockIdx.x * BN;

    float c[4][4][4] = {};

    // load lambdas: 512 float4 chunks each, 2 per thread
    auto loadA = [&](int stage, int k0) {
        #pragma unroll
        for (int i = 0; i < 2; i++) {
            int ch = tid + i * 256;
            int r = ch >> 2, c4 = ch & 3;
            cp_async16(&As[stage][r][c4 * 4], Ab + (size_t)(m0 + r) * K + k0 + c4 * 4);
        }
    };
    auto loadB = [&](int stage, int k0) {
        #pragma unroll
        for (int i = 0; i < 2; i++) {
            int ch = tid + i * 256;
            int r = ch >> 5, c4 = ch & 31;
            cp_async16(&Bs[stage][r][c4 * 4], Bb + (size_t)(k0 + r) * N + n0 + c4 * 4);
        }
    };

    loadA(0, 0); loadB(0, 0);
    cp_commit();

    const int T = K / BK;
    int p = 0;
    for (int t = 0; t < T; t++) {
        cp_wait0();
        __syncthreads();
        if (t + 1 < T) {
            loadA(p ^ 1, (t + 1) * BK);
            loadB(p ^ 1, (t + 1) * BK);
            cp_commit();
        }

        #pragma unroll
        for (int ks = 0; ks < BK; ks += 8) {
            uint32_t a[4][4], b[4][2];
            #pragma unroll
            for (int mt = 0; mt < 4; mt++) {
                int m = wm * 64 + mt * 16 + g;
                a[mt][0] = __float_as_uint(As[p][m    ][ks + t4    ]);
                a[mt][1] = __float_as_uint(As[p][m + 8][ks + t4    ]);
                a[mt][2] = __float_as_uint(As[p][m    ][ks + t4 + 4]);
                a[mt][3] = __float_as_uint(As[p][m + 8][ks + t4 + 4]);
            }
            #pragma unroll
            for (int nt = 0; nt < 4; nt++) {
                int n = wn * 32 + nt * 8 + g;
                b[nt][0] = __float_as_uint(Bs[p][ks + t4    ][n]);
                b[nt][1] = __float_as_uint(Bs[p][ks + t4 + 4][n]);
            }
            #pragma unroll
            for (int mt = 0; mt < 4; mt++)
                #pragma unroll
                for (int nt = 0; nt < 4; nt++)
                    mma_tf32(c[mt][nt], a[mt][0], a[mt][1], a[mt][2], a[mt][3],
                             b[nt][0], b[nt][1]);
        }
        p ^= 1;
    }

    // epilogue: (acc + bias) * alpha, optional relu; float2 stores
    #pragma unroll
    for (int mt = 0; mt < 4; mt++) {
        #pragma unroll
        for (int nt = 0; nt < 4; nt++) {
            int col = n0 + wn * 32 + nt * 8 + 2 * t4;
            float b0 = 0.f, b1 = 0.f;
            if (HASBIAS) { b0 = bias[col]; b1 = bias[col + 1]; }
            #pragma unroll
            for (int h = 0; h < 2; h++) {
                int row = m0 + wm * 64 + mt * 16 + g + h * 8;
                float v0 = (c[mt][nt][2 * h + 0] + b0) * alpha;
                float v1 = (c[mt][nt][2 * h + 1] + b1) * alpha;
                if (RELU) { v0 = fmaxf(v0, 0.f); v1 = fmaxf(v1, 0.f); }
                float2 st = make_float2(v0, v1);
                *(float2*)&Cb[(size_t)row * N + col] = st;
            }
        }
    }
}

// ---------------- transpose per batch: in [B][S][D] -> out [B][D][S] ----------------
__global__ void transpose_bsd(const float* __restrict__ in, float* __restrict__ out)
{
    __shared__ float tile[32][33];
    const int b = blockIdx.z;
    const int s0 = blockIdx.x * 32;
    const int d0 = blockIdx.y * 32;
    const float* ib = in  + (size_t)b * SS * DM;
    float*       ob = out + (size_t)b * DM * SS;

    int tx = threadIdx.x, ty = threadIdx.y;  // 32 x 8
    #pragma unroll
    for (int i = 0; i < 4; i++)
        tile[ty + i * 8][tx] = ib[(size_t)(s0 + ty + i * 8) * DM + d0 + tx];
    __syncthreads();
    #pragma unroll
    for (int i = 0; i < 4; i++)
        ob[(size_t)(d0 + ty + i * 8) * SS + s0 + tx] = tile[tx][ty + i * 8];
}

// ---------------- block reductions ----------------
__device__ __forceinline__ float blockAllReduceSum(float v) {
    __shared__ float sh[33];
    #pragma unroll
    for (int o = 16; o; o >>= 1) v += __shfl_xor_sync(0xffffffffu, v, o);
    int w = threadIdx.x >> 5;
    if ((threadIdx.x & 31) == 0) sh[w] = v;
    __syncthreads();
    if (threadIdx.x == 0) {
        float t = 0.f;
        int nw = blockDim.x >> 5;
        for (int i = 0; i < nw; i++) t += sh[i];
        sh[32] = t;
    }
    __syncthreads();
    float r = sh[32];
    __syncthreads();
    return r;
}

__device__ __forceinline__ float blockAllReduceMax(float v) {
    __shared__ float sh[33];
    #pragma unroll
    for (int o = 16; o; o >>= 1) v = fmaxf(v, __shfl_xor_sync(0xffffffffu, v, o));
    int w = threadIdx.x >> 5;
    if ((threadIdx.x & 31) == 0) sh[w] = v;
    __syncthreads();
    if (threadIdx.x == 0) {
        float t = -3.4e38f;
        int nw = blockDim.x >> 5;
        for (int i = 0; i < nw; i++) t = fmaxf(t, sh[i]);
        sh[32] = t;
    }
    __syncthreads();
    float r = sh[32];
    __syncthreads();
    return r;
}

// ---------------- row softmax (in place), cols = 2048, 256 threads, float4 ----------------
__global__ void softmax_kernel(float* __restrict__ Sp)
{
    float4* row = (float4*)(Sp + (size_t)blockIdx.x * SS);
    const int tid = threadIdx.x;

    float4 v[2];
    v[0] = row[tid];
    v[1] = row[tid + 256];

    float m = -3.4e38f;
    #pragma unroll
    for (int i = 0; i < 2; i++)
        m = fmaxf(m, fmaxf(fmaxf(v[i].x, v[i].y), fmaxf(v[i].z, v[i].w)));
    m = blockAllReduceMax(m);

    float s = 0.f;
    #pragma unroll
    for (int i = 0; i < 2; i++) {
        v[i].x = __expf(v[i].x - m); v[i].y = __expf(v[i].y - m);
        v[i].z = __expf(v[i].z - m); v[i].w = __expf(v[i].w - m);
        s += v[i].x + v[i].y + v[i].z + v[i].w;
    }
    s = blockAllReduceSum(s);
    float inv = 1.f / s;

    #pragma unroll
    for (int i = 0; i < 2; i++) {
        v[i].x *= inv; v[i].y *= inv; v[i].z *= inv; v[i].w *= inv;
    }
    row[tid]       = v[0];
    row[tid + 256] = v[1];
}

// ---------------- fused residual add + LayerNorm, D = 512, 256 threads ----------------
__global__ void add_ln_kernel(const float* __restrict__ a, const float* __restrict__ b,
                              const float* __restrict__ gamma, const float* __restrict__ beta,
                              float* __restrict__ out)
{
    const size_t row = blockIdx.x;
    const int tid = threadIdx.x;
    const float* ar = a + row * DM;
    const float* br = b + row * DM;

    float v0 = ar[tid]       + br[tid];
    float v1 = ar[tid + 256] + br[tid + 256];

    float s  = blockAllReduceSum(v0 + v1);
    float sq = blockAllReduceSum(v0 * v0 + v1 * v1);

    float mean = s * (1.f / DM);
    float var  = sq * (1.f / DM) - mean * mean;
    float inv  = rsqrtf(var + 1e-5f);

    float* o = out + row * DM;
    o[tid]       = (v0 - mean) * inv * gamma[tid]       + beta[tid];
    o[tid + 256] = (v1 - mean) * inv * gamma[tid + 256] + beta[tid + 256];
}

// ---------------- launch ----------------
extern "C" void kernel_launch(void* const* d_in, const int* in_sizes, int n_in,
                              void* d_out, int out_size)
{
    const float* q  = (const float*)d_in[0];
    const float* k  = (const float*)d_in[1];
    const float* v  = (const float*)d_in[2];
    const float* x  = (const float*)d_in[3];
    const float* Wq = (const float*)d_in[4];
    const float* bq = (const float*)d_in[5];
    const float* Wk = (const float*)d_in[6];
    const float* bk = (const float*)d_in[7];
    const float* Wv = (const float*)d_in[8];
    const float* bv = (const float*)d_in[9];
    const float* g1 = (const float*)d_in[10];
    const float* be1= (const float*)d_in[11];
    const float* W1 = (const float*)d_in[12];
    const float* b1 = (const float*)d_in[13];
    const float* W2 = (const float*)d_in[14];
    const float* b2 = (const float*)d_in[15];
    const float* g2 = (const float*)d_in[16];
    const float* be2= (const float*)d_in[17];
    float* out = (float*)d_out;

    float *pQ, *pK, *pKT, *pV, *pS, *pAttn, *pH, *pF, *pF2;
    cudaGetSymbolAddress((void**)&pQ,    g_Q);
    cudaGetSymbolAddress((void**)&pK,    g_K);
    cudaGetSymbolAddress((void**)&pKT,   g_KT);
    cudaGetSymbolAddress((void**)&pV,    g_V);
    cudaGetSymbolAddress((void**)&pS,    g_Sc);
    cudaGetSymbolAddress((void**)&pAttn, g_attn);
    cudaGetSymbolAddress((void**)&pH,    g_h);
    cudaGetSymbolAddress((void**)&pF,    g_f);
    cudaGetSymbolAddress((void**)&pF2,   g_f2);

    const float inv_sqrt_d = 1.f / sqrtf((float)DM);

    // 1) QKV projections (1/sqrt(d) folded into Q)
    {
        dim3 grid(DM / BN, ROWS / BM, 1);
        gemm_tc<1, 0><<<grid, 256>>>(q, Wq, bq, pQ, ROWS, DM, DM, 0, 0, 0, inv_sqrt_d);
        gemm_tc<1, 0><<<grid, 256>>>(k, Wk, bk, pK, ROWS, DM, DM, 0, 0, 0, 1.f);
        gemm_tc<1, 0><<<grid, 256>>>(v, Wv, bv, pV, ROWS, DM, DM, 0, 0, 0, 1.f);
    }

    // 2) K -> KT per batch
    {
        dim3 grid(SS / 32, DM / 32, BB);
        transpose_bsd<<<grid, dim3(32, 8)>>>(pK, pKT);
    }

    // 3) scores = Qs @ KT (NN), per batch
    {
        dim3 grid(SS / BN, SS / BM, BB);
        gemm_tc<0, 0><<<grid, 256>>>(pQ, pKT, nullptr, pS, SS, SS, DM,
                                     (size_t)SS * DM, (size_t)DM * SS, (size_t)SS * SS, 1.f);
    }

    // 4) softmax
    softmax_kernel<<<BB * SS, 256>>>(pS);

    // 5) attn = P @ V, per batch
    {
        dim3 grid(DM / BN, SS / BM, BB);
        gemm_tc<0, 0><<<grid, 256>>>(pS, pV, nullptr, pAttn, SS, DM, SS,
                                     (size_t)SS * SS, (size_t)SS * DM, (size_t)SS * DM, 1.f);
    }

    // 6) h = LN(attn + x)
    add_ln_kernel<<<ROWS, 256>>>(pAttn, x, g1, be1, pH);

    // 7) f = relu(h @ W1 + b1)
    {
        dim3 grid(DF / BN, ROWS / BM, 1);
        gemm_tc<1, 1><<<grid, 256>>>(pH, W1, b1, pF, ROWS, DF, DM, 0, 0, 0, 1.f);
    }

    // 8) f2 = f @ W2 + b2
    {
        dim3 grid(DM / BN, ROWS / BM, 1);
        gemm_tc<1, 0><<<grid, 256>>>(pF, W2, b2, pF2, ROWS, DM, DF, 0, 0, 0, 1.f);
    }

    // 9) out = LN(f2 + h)
    add_ln_kernel<<<ROWS, 256>>>(pF2, pH, g2, be2, out);
}

// round 3
// speedup vs baseline: 4.0956x; 1.1396x over previous
#include <cuda_runtime.h>
#include <math.h>
#include <stdint.h>

// Problem constants
#define BB   4
#define SS   2048
#define DM   512
#define DF   2048
#define ROWS (BB*SS)   // 8192

// GEMM tiling (tensor core)
#define BM 128
#define BN 128
#define BK 32
#define APAD 4
#define BPAD 8
#define ASTG (BM*(BK+APAD))     // 128*36 = 4608 floats per stage
#define BSTG (BK*(BN+BPAD))     // 32*136 = 4352 floats per stage
#define NSTAGE 3
#define SMEM_BYTES ((NSTAGE*ASTG + NSTAGE*BSTG)*4)   // 107520 B

// ---------------- scratch (device globals; no runtime alloc allowed) ----------------
__device__ float g_Q[ROWS*DM];
__device__ float g_K[ROWS*DM];
__device__ float g_KT[ROWS*DM];            // K transposed per batch: [B][D][S]
__device__ float g_V[ROWS*DM];
__device__ float g_Sc[(size_t)BB*SS*SS];   // attention scores / probs (64 MB)
__device__ float g_attn[ROWS*DM];
__device__ float g_h[ROWS*DM];
__device__ float g_f[ROWS*DF];             // FFN hidden (64 MB)
__device__ float g_f2[ROWS*DM];

// ---------------- helpers ----------------
__device__ __forceinline__ uint32_t smem_u32(const void* p) {
    return (uint32_t)__cvta_generic_to_shared(p);
}
__device__ __forceinline__ void cp_async16(void* dst, const void* src) {
    asm volatile("cp.async.cg.shared.global [%0], [%1], 16;"
                 :: "r"(smem_u32(dst)), "l"(src));
}
__device__ __forceinline__ void cp_commit() {
    asm volatile("cp.async.commit_group;");
}
__device__ __forceinline__ void cp_wait1() {
    asm volatile("cp.async.wait_group 1;");
}

__device__ __forceinline__ void mma_tf32(float c[4],
                                         uint32_t a0, uint32_t a1, uint32_t a2, uint32_t a3,
                                         uint32_t b0, uint32_t b1) {
    asm volatile(
        "mma.sync.aligned.m16n8k8.row.col.f32.tf32.tf32.f32 "
        "{%0,%1,%2,%3}, {%4,%5,%6,%7}, {%8,%9}, {%0,%1,%2,%3};"
        : "+f"(c[0]), "+f"(c[1]), "+f"(c[2]), "+f"(c[3])
        : "r"(a0), "r"(a1), "r"(a2), "r"(a3), "r"(b0), "r"(b1));
}

// ---------------- tensor-core GEMM NN: C = alpha*(A[M,K] @ B[K,N] + bias), relu opt ----------------
// A,B,C row-major; M%128==0, N%128==0, K%32==0. Batched via blockIdx.z + strides.
// 3-stage cp.async pipeline, 128x128x32 CTA tile, 8 warps x (64x32).
template<int HASBIAS, int RELU>
__global__ void __launch_bounds__(256, 2)
gemm_tc(const float* __restrict__ A, const float* __restrict__ B,
        const float* __restrict__ bias, float* __restrict__ C,
        int M, int N, int K, size_t sA, size_t sB, size_t sC, float alpha)
{
    extern __shared__ float sm[];
    // As stage s: sm[s*ASTG + m*(BK+APAD) + k]
    // Bs stage s: sm[NSTAGE*ASTG + s*BSTG + k*(BN+BPAD) + n]

    const float* Ab = A + (size_t)blockIdx.z * sA;
    const float* Bb = B + (size_t)blockIdx.z * sB;
    float*       Cb = C + (size_t)blockIdx.z * sC;

    const int tid  = threadIdx.x;
    const int wid  = tid >> 5, lane = tid & 31;
    const int g    = lane >> 2, t4 = lane & 3;
    const int wm   = wid >> 2, wn = wid & 3;         // 2 x 4 warp grid
    const int m0   = blockIdx.y * BM;
    const int n0   = blockIdx.x * BN;

    float c[4][4][4] = {};

    auto loadA = [&](int stage, int k0) {
        float* base = sm + stage * ASTG;
        #pragma unroll
        for (int i = 0; i < 4; i++) {
            int ch = tid + i * 256;                  // 1024 chunks: 128 rows x 8
            int r = ch >> 3, c4 = ch & 7;
            cp_async16(base + r * (BK + APAD) + c4 * 4,
                       Ab + (size_t)(m0 + r) * K + k0 + c4 * 4);
        }
    };
    auto loadB = [&](int stage, int k0) {
        float* base = sm + NSTAGE * ASTG + stage * BSTG;
        #pragma unroll
        for (int i = 0; i < 4; i++) {
            int ch = tid + i * 256;                  // 1024 chunks: 32 rows x 32
            int r = ch >> 5, c4 = ch & 31;
            cp_async16(base + r * (BN + BPAD) + c4 * 4,
                       Bb + (size_t)(k0 + r) * N + n0 + c4 * 4);
        }
    };

    const int T = K / BK;

    loadA(0, 0); loadB(0, 0);
    cp_commit();
    if (T > 1) { loadA(1, BK); loadB(1, BK); }
    cp_commit();

    for (int t = 0; t < T; t++) {
        cp_wait1();
        __syncthreads();
        int tn = t + 2;
        if (tn < T) { loadA(tn % NSTAGE, tn * BK); loadB(tn % NSTAGE, tn * BK); }
        cp_commit();

        const int p = t % NSTAGE;
        const float* Asb = sm + p * ASTG;
        const float* Bsb = sm + NSTAGE * ASTG + p * BSTG;

        #pragma unroll
        for (int ks = 0; ks < BK; ks += 8) {
            uint32_t a[4][4], b[4][2];
            #pragma unroll
            for (int mt = 0; mt < 4; mt++) {
                int m = wm * 64 + mt * 16 + g;
                const float* r0 = Asb + (size_t)m * (BK + APAD) + ks;
                const float* r1 = r0 + 8 * (BK + APAD);
                a[mt][0] = __float_as_uint(r0[t4]);
                a[mt][1] = __float_as_uint(r1[t4]);
                a[mt][2] = __float_as_uint(r0[t4 + 4]);
                a[mt][3] = __float_as_uint(r1[t4 + 4]);
            }
            #pragma unroll
            for (int nt = 0; nt < 4; nt++) {
                int n = wn * 32 + nt * 8 + g;
                b[nt][0] = __float_as_uint(Bsb[(ks + t4) * (BN + BPAD) + n]);
                b[nt][1] = __float_as_uint(Bsb[(ks + t4 + 4) * (BN + BPAD) + n]);
            }
            #pragma unroll
            for (int mt = 0; mt < 4; mt++)
                #pragma unroll
                for (int nt = 0; nt < 4; nt++)
                    mma_tf32(c[mt][nt], a[mt][0], a[mt][1], a[mt][2], a[mt][3],
                             b[nt][0], b[nt][1]);
        }
    }

    // epilogue: (acc + bias) * alpha, optional relu; float2 stores
    #pragma unroll
    for (int mt = 0; mt < 4; mt++) {
        #pragma unroll
        for (int nt = 0; nt < 4; nt++) {
            int col = n0 + wn * 32 + nt * 8 + 2 * t4;
            float b0 = 0.f, b1 = 0.f;
            if (HASBIAS) { b0 = bias[col]; b1 = bias[col + 1]; }
            #pragma unroll
            for (int h = 0; h < 2; h++) {
                int row = m0 + wm * 64 + mt * 16 + g + h * 8;
                float v0 = (c[mt][nt][2 * h + 0] + b0) * alpha;
                float v1 = (c[mt][nt][2 * h + 1] + b1) * alpha;
                if (RELU) { v0 = fmaxf(v0, 0.f); v1 = fmaxf(v1, 0.f); }
                float2 st = make_float2(v0, v1);
                *(float2*)&Cb[(size_t)row * N + col] = st;
            }
        }
    }
}

// ---------------- transpose per batch: in [B][S][D] -> out [B][D][S] ----------------
__global__ void transpose_bsd(const float* __restrict__ in, float* __restrict__ out)
{
    __shared__ float tile[32][33];
    const int b = blockIdx.z;
    const int s0 = blockIdx.x * 32;
    const int d0 = blockIdx.y * 32;
    const float* ib = in  + (size_t)b * SS * DM;
    float*       ob = out + (size_t)b * DM * SS;

    int tx = threadIdx.x, ty = threadIdx.y;  // 32 x 8
    #pragma unroll
    for (int i = 0; i < 4; i++)
        tile[ty + i * 8][tx] = ib[(size_t)(s0 + ty + i * 8) * DM + d0 + tx];
    __syncthreads();
    #pragma unroll
    for (int i = 0; i < 4; i++)
        ob[(size_t)(d0 + ty + i * 8) * SS + s0 + tx] = tile[tx][ty + i * 8];
}

// ---------------- block reductions ----------------
__device__ __forceinline__ float blockAllReduceSum(float v) {
    __shared__ float sh[33];
    #pragma unroll
    for (int o = 16; o; o >>= 1) v += __shfl_xor_sync(0xffffffffu, v, o);
    int w = threadIdx.x >> 5;
    if ((threadIdx.x & 31) == 0) sh[w] = v;
    __syncthreads();
    if (threadIdx.x == 0) {
        float t = 0.f;
        int nw = blockDim.x >> 5;
        for (int i = 0; i < nw; i++) t += sh[i];
        sh[32] = t;
    }
    __syncthreads();
    float r = sh[32];
    __syncthreads();
    return r;
}

__device__ __forceinline__ float blockAllReduceMax(float v) {
    __shared__ float sh[33];
    #pragma unroll
    for (int o = 16; o; o >>= 1) v = fmaxf(v, __shfl_xor_sync(0xffffffffu, v, o));
    int w = threadIdx.x >> 5;
    if ((threadIdx.x & 31) == 0) sh[w] = v;
    __syncthreads();
    if (threadIdx.x == 0) {
        float t = -3.4e38f;
        int nw = blockDim.x >> 5;
        for (int i = 0; i < nw; i++) t = fmaxf(t, sh[i]);
        sh[32] = t;
    }
    __syncthreads();
    float r = sh[32];
    __syncthreads();
    return r;
}

// ---------------- row softmax (in place), cols = 2048, 256 threads, float4 ----------------
__global__ void softmax_kernel(float* __restrict__ Sp)
{
    float4* row = (float4*)(Sp + (size_t)blockIdx.x * SS);
    const int tid = threadIdx.x;

    float4 v[2];
    v[0] = row[tid];
    v[1] = row[tid + 256];

    float m = -3.4e38f;
    #pragma unroll
    for (int i = 0; i < 2; i++)
        m = fmaxf(m, fmaxf(fmaxf(v[i].x, v[i].y), fmaxf(v[i].z, v[i].w)));
    m = blockAllReduceMax(m);

    float s = 0.f;
    #pragma unroll
    for (int i = 0; i < 2; i++) {
        v[i].x = __expf(v[i].x - m); v[i].y = __expf(v[i].y - m);
        v[i].z = __expf(v[i].z - m); v[i].w = __expf(v[i].w - m);
        s += v[i].x + v[i].y + v[i].z + v[i].w;
    }
    s = blockAllReduceSum(s);
    float inv = 1.f / s;

    #pragma unroll
    for (int i = 0; i < 2; i++) {
        v[i].x *= inv; v[i].y *= inv; v[i].z *= inv; v[i].w *= inv;
    }
    row[tid]       = v[0];
    row[tid + 256] = v[1];
}

// ---------------- fused residual add + LayerNorm, D = 512, 256 threads ----------------
__global__ void add_ln_kernel(const float* __restrict__ a, const float* __restrict__ b,
                              const float* __restrict__ gamma, const float* __restrict__ beta,
                              float* __restrict__ out)
{
    const size_t row = blockIdx.x;
    const int tid = threadIdx.x;
    const float* ar = a + row * DM;
    const float* br = b + row * DM;

    float v0 = ar[tid]       + br[tid];
    float v1 = ar[tid + 256] + br[tid + 256];

    float s  = blockAllReduceSum(v0 + v1);
    float sq = blockAllReduceSum(v0 * v0 + v1 * v1);

    float mean = s * (1.f / DM);
    float var  = sq * (1.f / DM) - mean * mean;
    float inv  = rsqrtf(var + 1e-5f);

    float* o = out + row * DM;
    o[tid]       = (v0 - mean) * inv * gamma[tid]       + beta[tid];
    o[tid + 256] = (v1 - mean) * inv * gamma[tid + 256] + beta[tid + 256];
}

// ---------------- launch ----------------
extern "C" void kernel_launch(void* const* d_in, const int* in_sizes, int n_in,
                              void* d_out, int out_size)
{
    const float* q  = (const float*)d_in[0];
    const float* k  = (const float*)d_in[1];
    const float* v  = (const float*)d_in[2];
    const float* x  = (const float*)d_in[3];
    const float* Wq = (const float*)d_in[4];
    const float* bq = (const float*)d_in[5];
    const float* Wk = (const float*)d_in[6];
    const float* bk = (const float*)d_in[7];
    const float* Wv = (const float*)d_in[8];
    const float* bv = (const float*)d_in[9];
    const float* g1 = (const float*)d_in[10];
    const float* be1= (const float*)d_in[11];
    const float* W1 = (const float*)d_in[12];
    const float* b1 = (const float*)d_in[13];
    const float* W2 = (const float*)d_in[14];
    const float* b2 = (const float*)d_in[15];
    const float* g2 = (const float*)d_in[16];
    const float* be2= (const float*)d_in[17];
    float* out = (float*)d_out;

    float *pQ, *pK, *pKT, *pV, *pS, *pAttn, *pH, *pF, *pF2;
    cudaGetSymbolAddress((void**)&pQ,    g_Q);
    cudaGetSymbolAddress((void**)&pK,    g_K);
    cudaGetSymbolAddress((void**)&pKT,   g_KT);
    cudaGetSymbolAddress((void**)&pV,    g_V);
    cudaGetSymbolAddress((void**)&pS,    g_Sc);
    cudaGetSymbolAddress((void**)&pAttn, g_attn);
    cudaGetSymbolAddress((void**)&pH,    g_h);
    cudaGetSymbolAddress((void**)&pF,    g_f);
    cudaGetSymbolAddress((void**)&pF2,   g_f2);

    // allow >48KB dynamic smem (idempotent; cheap host-side calls)
    cudaFuncSetAttribute(gemm_tc<1,0>, cudaFuncAttributeMaxDynamicSharedMemorySize, SMEM_BYTES);
    cudaFuncSetAttribute(gemm_tc<0,0>, cudaFuncAttributeMaxDynamicSharedMemorySize, SMEM_BYTES);
    cudaFuncSetAttribute(gemm_tc<1,1>, cudaFuncAttributeMaxDynamicSharedMemorySize, SMEM_BYTES);

    const float inv_sqrt_d = 1.f / sqrtf((float)DM);

    // 1) QKV projections (1/sqrt(d) folded into Q)
    {
        dim3 grid(DM / BN, ROWS / BM, 1);
        gemm_tc<1, 0><<<grid, 256, SMEM_BYTES>>>(q, Wq, bq, pQ, ROWS, DM, DM, 0, 0, 0, inv_sqrt_d);
        gemm_tc<1, 0><<<grid, 256, SMEM_BYTES>>>(k, Wk, bk, pK, ROWS, DM, DM, 0, 0, 0, 1.f);
        gemm_tc<1, 0><<<grid, 256, SMEM_BYTES>>>(v, Wv, bv, pV, ROWS, DM, DM, 0, 0, 0, 1.f);
    }

    // 2) K -> KT per batch
    {
        dim3 grid(SS / 32, DM / 32, BB);
        transpose_bsd<<<grid, dim3(32, 8)>>>(pK, pKT);
    }

    // 3) scores = Qs @ KT (NN), per batch
    {
        dim3 grid(SS / BN, SS / BM, BB);
        gemm_tc<0, 0><<<grid, 256, SMEM_BYTES>>>(pQ, pKT, nullptr, pS, SS, SS, DM,
                                     (size_t)SS * DM, (size_t)DM * SS, (size_t)SS * SS, 1.f);
    }

    // 4) softmax
    softmax_kernel<<<BB * SS, 256>>>(pS);

    // 5) attn = P @ V, per batch
    {
        dim3 grid(DM / BN, SS / BM, BB);
        gemm_tc<0, 0><<<grid, 256, SMEM_BYTES>>>(pS, pV, nullptr, pAttn, SS, DM, SS,
                                     (size_t)SS * SS, (size_t)SS * DM, (size_t)SS * DM, 1.f);
    }

    // 6) h = LN(attn + x)
    add_ln_kernel<<<ROWS, 256>>>(pAttn, x, g1, be1, pH);

    // 7) f = relu(h @ W1 + b1)
    {
        dim3 grid(DF / BN, ROWS / BM, 1);
        gemm_tc<1, 1><<<grid, 256, SMEM_BYTES>>>(pH, W1, b1, pF, ROWS, DF, DM, 0, 0, 0, 1.f);
    }

    // 8) f2 = f @ W2 + b2
    {
        dim3 grid(DM / BN, ROWS / BM, 1);
        gemm_tc<1, 0><<<grid, 256, SMEM_BYTES>>>(pF, W2, b2, pF2, ROWS, DM, DF, 0, 0, 0, 1.f);
    }

    // 9) out = LN(f2 + h)
    add_ln_kernel<<<ROWS, 256>>>(pF2, pH, g2, be2, out);
}

// round 5
// speedup vs baseline: 5.6380x; 1.3766x over previous
#include <cuda_runtime.h>
#include <cuda_fp16.h>
#include <math.h>
#include <stdint.h>

// Problem constants
#define BB   4
#define SS   2048
#define DM   512
#define DF   2048
#define ROWS (BB*SS)   // 8192

// fp16 tensor-core GEMM tiling
#define BM 128
#define BN 128
#define BKH 64                  // K per tile, in halves (128 B rows)
#define RP  72                  // padded row pitch in halves (144 B)
#define ASTG_H (BM*RP)          // 9216 halves
#define STG_H (2*ASTG_H)        // A + B per stage = 18432 halves
#define NSTAGE 3
#define SMEM_H (NSTAGE*STG_H*2) // 110592 bytes

// ---------------- scratch (device globals; no runtime alloc allowed) ----------------
__device__ __half g_qh[ROWS*DM];
__device__ __half g_kh[ROWS*DM];
__device__ __half g_vh[ROWS*DM];
__device__ __half g_Qh[ROWS*DM];
__device__ __half g_Kh[ROWS*DM];
__device__ __half g_Vh[ROWS*DM];
__device__ __half g_VTh[ROWS*DM];             // V^T per batch [B][D][S]
__device__ float  g_Sc[(size_t)BB*SS*SS];     // fp32 scores (64 MB)
__device__ __half g_Ph[(size_t)BB*SS*SS];     // half probs (32 MB)
__device__ float  g_attn[ROWS*DM];
__device__ float  g_h[ROWS*DM];
__device__ __half g_hh[ROWS*DM];
__device__ __half g_f[ROWS*DF];               // FFN hidden, half
__device__ float  g_f2[ROWS*DM];
__device__ __half g_WqT[DM*DM];
__device__ __half g_WkT[DM*DM];
__device__ __half g_WvT[DM*DM];
__device__ __half g_W1T[(size_t)DF*DM];
__device__ __half g_W2T[(size_t)DM*DF];

// ---------------- helpers ----------------
__device__ __forceinline__ uint32_t smem_u32(const void* p) {
    return (uint32_t)__cvta_generic_to_shared(p);
}
__device__ __forceinline__ void cp_async16(void* dst, const void* src) {
    asm volatile("cp.async.cg.shared.global [%0], [%1], 16;"
                 :: "r"(smem_u32(dst)), "l"(src));
}
__device__ __forceinline__ void cp_commit() {
    asm volatile("cp.async.commit_group;");
}
__device__ __forceinline__ void cp_wait1() {
    asm volatile("cp.async.wait_group 1;");
}

__device__ __forceinline__ void mma_f16(float c[4],
                                        uint32_t a0, uint32_t a1, uint32_t a2, uint32_t a3,
                                        uint32_t b0, uint32_t b1) {
    asm volatile(
        "mma.sync.aligned.m16n8k16.row.col.f32.f16.f16.f32 "
        "{%0,%1,%2,%3}, {%4,%5,%6,%7}, {%8,%9}, {%0,%1,%2,%3};"
        : "+f"(c[0]), "+f"(c[1]), "+f"(c[2]), "+f"(c[3])
        : "r"(a0), "r"(a1), "r"(a2), "r"(a3), "r"(b0), "r"(b1));
}

// ---------------- fp16 tensor-core GEMM NT ----------------
// C = alpha*(A[M,K] @ Bt[N,K]^T + bias); A,Bt half K-major; C float or half.
// M%128==0, N%128==0, K%64==0. Batched via blockIdx.z + strides.
template<int HASBIAS, int RELU, int OUTH>
__global__ void __launch_bounds__(256, 1)
gemm_h(const __half* __restrict__ A, const __half* __restrict__ Bt,
       const float* __restrict__ bias, void* __restrict__ Cv,
       int M, int N, int K, size_t sA, size_t sB, size_t sC, float alpha)
{
    extern __shared__ __half hsm[];

    const __half* Ab = A  + (size_t)blockIdx.z * sA;
    const __half* Bb = Bt + (size_t)blockIdx.z * sB;

    const int tid = threadIdx.x;
    const int wid = tid >> 5, lane = tid & 31;
    const int g   = lane >> 2, t4 = lane & 3;
    const int wm  = wid >> 2, wn = wid & 3;        // 2 x 4 warp grid, warp tile 64x32
    const int m0  = blockIdx.y * BM;
    const int n0  = blockIdx.x * BN;

    float c[4][4][4] = {};

    auto aBase = [&](int s) { return hsm + s * STG_H; };
    auto bBase = [&](int s) { return hsm + s * STG_H + ASTG_H; };

    auto loadA = [&](int s, int k0) {
        __half* base = aBase(s);
        #pragma unroll
        for (int i = 0; i < 4; i++) {
            int ch = tid + i * 256;                // 1024 chunks: 128 rows x 8 x 16B
            int r = ch >> 3, cc = ch & 7;
            cp_async16(base + r * RP + cc * 8,
                       Ab + (size_t)(m0 + r) * K + k0 + cc * 8);
        }
    };
    auto loadB = [&](int s, int k0) {
        __half* base = bBase(s);
        #pragma unroll
        for (int i = 0; i < 4; i++) {
            int ch = tid + i * 256;
            int r = ch >> 3, cc = ch & 7;
            cp_async16(base + r * RP + cc * 8,
                       Bb + (size_t)(n0 + r) * K + k0 + cc * 8);
        }
    };

    const int T = K / BKH;

    loadA(0, 0);   loadB(0, 0);   cp_commit();
    loadA(1, BKH); loadB(1, BKH); cp_commit();

    for (int t = 0; t < T; t++) {
        cp_wait1();
        __syncthreads();
        int tn = t + 2;
        if (tn < T) { loadA(tn % NSTAGE, tn * BKH); loadB(tn % NSTAGE, tn * BKH); }
        cp_commit();

        const int p = t % NSTAGE;
        const __half* Asb = aBase(p);
        const __half* Bsb = bBase(p);

        #pragma unroll
        for (int ks = 0; ks < 4; ks++) {
            const int kh = ks * 16;
            uint32_t a[4][4], b[4][2];
            #pragma unroll
            for (int mt = 0; mt < 4; mt++) {
                const __half* pr = Asb + (size_t)(wm * 64 + mt * 16 + g) * RP + kh;
                a[mt][0] = *(const uint32_t*)(pr + 2 * t4);
                a[mt][1] = *(const uint32_t*)(pr + 8 * RP + 2 * t4);
                a[mt][2] = *(const uint32_t*)(pr + 2 * t4 + 8);
                a[mt][3] = *(const uint32_t*)(pr + 8 * RP + 2 * t4 + 8);
            }
            #pragma unroll
            for (int nt = 0; nt < 4; nt++) {
                const __half* pn = Bsb + (size_t)(wn * 32 + nt * 8 + g) * RP + kh;
                b[nt][0] = *(const uint32_t*)(pn + 2 * t4);
                b[nt][1] = *(const uint32_t*)(pn + 2 * t4 + 8);
            }
            #pragma unroll
            for (int mt = 0; mt < 4; mt++)
                #pragma unroll
                for (int nt = 0; nt < 4; nt++)
                    mma_f16(c[mt][nt], a[mt][0], a[mt][1], a[mt][2], a[mt][3],
                            b[nt][0], b[nt][1]);
        }
    }

    // epilogue
    #pragma unroll
    for (int mt = 0; mt < 4; mt++) {
        #pragma unroll
        for (int nt = 0; nt < 4; nt++) {
            const int col = n0 + wn * 32 + nt * 8 + 2 * t4;
            float b0 = 0.f, b1 = 0.f;
            if (HASBIAS) { b0 = bias[col]; b1 = bias[col + 1]; }
            #pragma unroll
            for (int h = 0; h < 2; h++) {
                const int row = m0 + wm * 64 + mt * 16 + g + h * 8;
                float v0 = (c[mt][nt][2 * h + 0] + b0) * alpha;
                float v1 = (c[mt][nt][2 * h + 1] + b1) * alpha;
                if (RELU) { v0 = fmaxf(v0, 0.f); v1 = fmaxf(v1, 0.f); }
                if (OUTH) {
                    __half* Cb = (__half*)Cv + (size_t)blockIdx.z * sC;
                    *(__half2*)&Cb[(size_t)row * N + col] = __floats2half2_rn(v0, v1);
                } else {
                    float* Cb = (float*)Cv + (size_t)blockIdx.z * sC;
                    *(float2*)&Cb[(size_t)row * N + col] = make_float2(v0, v1);
                }
            }
        }
    }
}

// ---------------- convert fp32 -> fp16 (elementwise, float4) ----------------
__global__ void f2h_kernel(const float* __restrict__ in, __half* __restrict__ out)
{
    const int i = (blockIdx.x * blockDim.x + threadIdx.x) * 4;
    float4 v = *(const float4*)(in + i);
    *(__half2*)(out + i)     = __floats2half2_rn(v.x, v.y);
    *(__half2*)(out + i + 2) = __floats2half2_rn(v.z, v.w);
}

// ---------------- transpose + convert: in fp32 [R][C] -> out half [C][R] ----------------
__global__ void transpose_f2h(const float* __restrict__ in, __half* __restrict__ out,
                              int R, int C)
{
    __shared__ float tile[32][33];
    const int r0 = blockIdx.x * 32;
    const int c0 = blockIdx.y * 32;
    const int tx = threadIdx.x, ty = threadIdx.y;    // 32 x 8
    #pragma unroll
    for (int i = 0; i < 4; i++)
        tile[ty + i * 8][tx] = in[(size_t)(r0 + ty + i * 8) * C + c0 + tx];
    __syncthreads();
    #pragma unroll
    for (int i = 0; i < 4; i++)
        out[(size_t)(c0 + ty + i * 8) * R + r0 + tx] = __float2half_rn(tile[tx][ty + i * 8]);
}

// ---------------- transpose half, per-batch: in [b][R][C] -> out [b][C][R] ----------------
__global__ void transpose_h(const __half* __restrict__ in, __half* __restrict__ out,
                            int R, int C, size_t sIn, size_t sOut)
{
    __shared__ __half tile[32][34];
    const __half* ib = in  + (size_t)blockIdx.z * sIn;
    __half*       ob = out + (size_t)blockIdx.z * sOut;
    const int r0 = blockIdx.x * 32;
    const int c0 = blockIdx.y * 32;
    const int tx = threadIdx.x, ty = threadIdx.y;
    #pragma unroll
    for (int i = 0; i < 4; i++)
        tile[ty + i * 8][tx] = ib[(size_t)(r0 + ty + i * 8) * C + c0 + tx];
    __syncthreads();
    #pragma unroll
    for (int i = 0; i < 4; i++)
        ob[(size_t)(c0 + ty + i * 8) * R + r0 + tx] = tile[tx][ty + i * 8];
}

// ---------------- block reductions ----------------
__device__ __forceinline__ float blockAllReduceSum(float v) {
    __shared__ float sh[33];
    #pragma unroll
    for (int o = 16; o; o >>= 1) v += __shfl_xor_sync(0xffffffffu, v, o);
    int w = threadIdx.x >> 5;
    if ((threadIdx.x & 31) == 0) sh[w] = v;
    __syncthreads();
    if (threadIdx.x == 0) {
        float t = 0.f;
        int nw = blockDim.x >> 5;
        for (int i = 0; i < nw; i++) t += sh[i];
        sh[32] = t;
    }
    __syncthreads();
    float r = sh[32];
    __syncthreads();
    return r;
}

__device__ __forceinline__ float blockAllReduceMax(float v) {
    __shared__ float sh[33];
    #pragma unroll
    for (int o = 16; o; o >>= 1) v = fmaxf(v, __shfl_xor_sync(0xffffffffu, v, o));
    int w = threadIdx.x >> 5;
    if ((threadIdx.x & 31) == 0) sh[w] = v;
    __syncthreads();
    if (threadIdx.x == 0) {
        float t = -3.4e38f;
        int nw = blockDim.x >> 5;
        for (int i = 0; i < nw; i++) t = fmaxf(t, sh[i]);
        sh[32] = t;
    }
    __syncthreads();
    float r = sh[32];
    __syncthreads();
    return r;
}

// ---------------- row softmax: fp32 scores -> half probs, cols = 2048 ----------------
__global__ void softmax_kernel(const float* __restrict__ Sp, __half* __restrict__ Pp)
{
    const float4* row = (const float4*)(Sp + (size_t)blockIdx.x * SS);
    __half* orow = Pp + (size_t)blockIdx.x * SS;
    const int tid = threadIdx.x;

    float4 v[2];
    v[0] = row[tid];
    v[1] = row[tid + 256];

    float m = -3.4e38f;
    #pragma unroll
    for (int i = 0; i < 2; i++)
        m = fmaxf(m, fmaxf(fmaxf(v[i].x, v[i].y), fmaxf(v[i].z, v[i].w)));
    m = blockAllReduceMax(m);

    float s = 0.f;
    #pragma unroll
    for (int i = 0; i < 2; i++) {
        v[i].x = __expf(v[i].x - m); v[i].y = __expf(v[i].y - m);
        v[i].z = __expf(v[i].z - m); v[i].w = __expf(v[i].w - m);
        s += v[i].x + v[i].y + v[i].z + v[i].w;
    }
    s = blockAllReduceSum(s);
    float inv = 1.f / s;

    #pragma unroll
    for (int i = 0; i < 2; i++) {
        int base = (i == 0 ? tid : tid + 256) * 4;
        *(__half2*)(orow + base)     = __floats2half2_rn(v[i].x * inv, v[i].y * inv);
        *(__half2*)(orow + base + 2) = __floats2half2_rn(v[i].z * inv, v[i].w * inv);
    }
}

// ---------------- fused residual add + LayerNorm (+ optional half copy) ----------------
template<int WRITEH>
__global__ void add_ln_kernel(const float* __restrict__ a, const float* __restrict__ b,
                              const float* __restrict__ gamma, const float* __restrict__ beta,
                              float* __restrict__ out, __half* __restrict__ outh)
{
    const size_t row = blockIdx.x;
    const int tid = threadIdx.x;
    const float* ar = a + row * DM;
    const float* br = b + row * DM;

    float v0 = ar[tid]       + br[tid];
    float v1 = ar[tid + 256] + br[tid + 256];

    float s  = blockAllReduceSum(v0 + v1);
    float sq = blockAllReduceSum(v0 * v0 + v1 * v1);

    float mean = s * (1.f / DM);
    float var  = sq * (1.f / DM) - mean * mean;
    float inv  = rsqrtf(var + 1e-5f);

    float o0 = (v0 - mean) * inv * gamma[tid]       + beta[tid];
    float o1 = (v1 - mean) * inv * gamma[tid + 256] + beta[tid + 256];

    float* o = out + row * DM;
    o[tid]       = o0;
    o[tid + 256] = o1;
    if (WRITEH) {
        __half* oh = outh + row * DM;
        oh[tid]       = __float2half_rn(o0);
        oh[tid + 256] = __float2half_rn(o1);
    }
}

// ---------------- launch ----------------
extern "C" void kernel_launch(void* const* d_in, const int* in_sizes, int n_in,
                              void* d_out, int out_size)
{
    const float* q  = (const float*)d_in[0];
    const float* k  = (const float*)d_in[1];
    const float* v  = (const float*)d_in[2];
    const float* x  = (const float*)d_in[3];
    const float* Wq = (const float*)d_in[4];
    const float* bq = (const float*)d_in[5];
    const float* Wk = (const float*)d_in[6];
    const float* bk = (const float*)d_in[7];
    const float* Wv = (const float*)d_in[8];
    const float* bv = (const float*)d_in[9];
    const float* g1 = (const float*)d_in[10];
    const float* be1= (const float*)d_in[11];
    const float* W1 = (const float*)d_in[12];
    const float* b1 = (const float*)d_in[13];
    const float* W2 = (const float*)d_in[14];
    const float* b2 = (const float*)d_in[15];
    const float* g2 = (const float*)d_in[16];
    const float* be2= (const float*)d_in[17];
    float* out = (float*)d_out;

    __half *pqh, *pkh, *pvh, *pQh, *pKh, *pVh, *pVTh, *pPh, *phh, *pf;
    __half *pWqT, *pWkT, *pWvT, *pW1T, *pW2T;
    float *pS, *pAttn, *pH, *pF2;
    cudaGetSymbolAddress((void**)&pqh,  g_qh);
    cudaGetSymbolAddress((void**)&pkh,  g_kh);
    cudaGetSymbolAddress((void**)&pvh,  g_vh);
    cudaGetSymbolAddress((void**)&pQh,  g_Qh);
    cudaGetSymbolAddress((void**)&pKh,  g_Kh);
    cudaGetSymbolAddress((void**)&pVh,  g_Vh);
    cudaGetSymbolAddress((void**)&pVTh, g_VTh);
    cudaGetSymbolAddress((void**)&pS,   g_Sc);
    cudaGetSymbolAddress((void**)&pPh,  g_Ph);
    cudaGetSymbolAddress((void**)&pAttn,g_attn);
    cudaGetSymbolAddress((void**)&pH,   g_h);
    cudaGetSymbolAddress((void**)&phh,  g_hh);
    cudaGetSymbolAddress((void**)&pf,   g_f);
    cudaGetSymbolAddress((void**)&pF2,  g_f2);
    cudaGetSymbolAddress((void**)&pWqT, g_WqT);
    cudaGetSymbolAddress((void**)&pWkT, g_WkT);
    cudaGetSymbolAddress((void**)&pWvT, g_WvT);
    cudaGetSymbolAddress((void**)&pW1T, g_W1T);
    cudaGetSymbolAddress((void**)&pW2T, g_W2T);

    cudaFuncSetAttribute(gemm_h<1,0,1>, cudaFuncAttributeMaxDynamicSharedMemorySize, SMEM_H);
    cudaFuncSetAttribute(gemm_h<0,0,0>, cudaFuncAttributeMaxDynamicSharedMemorySize, SMEM_H);
    cudaFuncSetAttribute(gemm_h<0,0,0>, cudaFuncAttributeMaxDynamicSharedMemorySize, SMEM_H);
    cudaFuncSetAttribute(gemm_h<1,1,1>, cudaFuncAttributeMaxDynamicSharedMemorySize, SMEM_H);
    cudaFuncSetAttribute(gemm_h<1,0,0>, cudaFuncAttributeMaxDynamicSharedMemorySize, SMEM_H);

    const float inv_sqrt_d = 1.f / sqrtf((float)DM);
    const dim3 t32x8(32, 8);

    // 0a) convert inputs to half
    f2h_kernel<<<ROWS * DM / 1024, 256>>>(q, pqh);
    f2h_kernel<<<ROWS * DM / 1024, 256>>>(k, pkh);
    f2h_kernel<<<ROWS * DM / 1024, 256>>>(v, pvh);

    // 0b) transpose + convert weights to half [N][K]
    transpose_f2h<<<dim3(DM/32, DM/32), t32x8>>>(Wq, pWqT, DM, DM);
    transpose_f2h<<<dim3(DM/32, DM/32), t32x8>>>(Wk, pWkT, DM, DM);
    transpose_f2h<<<dim3(DM/32, DM/32), t32x8>>>(Wv, pWvT, DM, DM);
    transpose_f2h<<<dim3(DM/32, DF/32), t32x8>>>(W1, pW1T, DM, DF);
    transpose_f2h<<<dim3(DF/32, DM/32), t32x8>>>(W2, pW2T, DF, DM);

    // 1) QKV projections -> half outputs (1/sqrt(d) folded into Q)
    {
        dim3 grid(DM / BN, ROWS / BM, 1);
        gemm_h<1,0,1><<<grid, 256, SMEM_H>>>(pqh, pWqT, bq, pQh, ROWS, DM, DM, 0, 0, 0, inv_sqrt_d);
        gemm_h<1,0,1><<<grid, 256, SMEM_H>>>(pkh, pWkT, bk, pKh, ROWS, DM, DM, 0, 0, 0, 1.f);
        gemm_h<1,0,1><<<grid, 256, SMEM_H>>>(pvh, pWvT, bv, pVh, ROWS, DM, DM, 0, 0, 0, 1.f);
    }

    // 2) V -> V^T per batch (half)
    transpose_h<<<dim3(SS/32, DM/32, BB), t32x8>>>(pVh, pVTh, SS, DM,
                                                   (size_t)SS*DM, (size_t)DM*SS);

    // 3) scores = Qs @ K^T -> fp32 (NT: B operand = K, K-major over D)
    {
        dim3 grid(SS / BN, SS / BM, BB);
        gemm_h<0,0,0><<<grid, 256, SMEM_H>>>(pQh, pKh, nullptr, pS, SS, SS, DM,
                                             (size_t)SS*DM, (size_t)SS*DM, (size_t)SS*SS, 1.f);
    }

    // 4) softmax fp32 -> half probs
    softmax_kernel<<<BB * SS, 256>>>(pS, pPh);

    // 5) attn = P @ V -> fp32 (NT with B = V^T [D,S])
    {
        dim3 grid(DM / BN, SS / BM, BB);
        gemm_h<0,0,0><<<grid, 256, SMEM_H>>>(pPh, pVTh, nullptr, pAttn, SS, DM, SS,
                                             (size_t)SS*SS, (size_t)DM*SS, (size_t)SS*DM, 1.f);
    }

    // 6) h = LN(attn + x), fp32 + half copy
    add_ln_kernel<1><<<ROWS, 256>>>(pAttn, x, g1, be1, pH, phh);

    // 7) f = relu(h @ W1 + b1) -> half
    {
        dim3 grid(DF / BN, ROWS / BM, 1);
        gemm_h<1,1,1><<<grid, 256, SMEM_H>>>(phh, pW1T, b1, pf, ROWS, DF, DM, 0, 0, 0, 1.f);
    }

    // 8) f2 = f @ W2 + b2 -> fp32
    {
        dim3 grid(DM / BN, ROWS / BM, 1);
        gemm_h<1,0,0><<<grid, 256, SMEM_H>>>(pf, pW2T, b2, pF2, ROWS, DM, DF, 0, 0, 0, 1.f);
    }

    // 9) out = LN(f2 + h)
    add_ln_kernel<0><<<ROWS, 256>>>(pF2, pH, g2, be2, out, nullptr);
}

// round 6
// speedup vs baseline: 6.7205x; 1.1920x over previous
#include <cuda_runtime.h>
#include <cuda_fp16.h>
#include <math.h>
#include <stdint.h>

// Problem constants
#define BB   4
#define SS   2048
#define DM   512
#define DF   2048
#define ROWS (BB*SS)   // 8192

// fp16 tensor-core GEMM tiling
#define BM 128
#define BN 128
#define BKH 64                  // K per tile, in halves (128 B rows)
#define RP  72                  // padded row pitch in halves (144 B)
#define ASTG_H (BM*RP)          // 9216 halves
#define STG_H (2*ASTG_H)        // A + B per stage = 18432 halves
#define NSTAGE 3
#define SMEM_H (NSTAGE*STG_H*2) // 110592 bytes

// ---------------- scratch (device globals; no runtime alloc allowed) ----------------
__device__ __half g_qh[ROWS*DM];
__device__ __half g_kh[ROWS*DM];
__device__ __half g_vh[ROWS*DM];
__device__ __half g_Qh[ROWS*DM];
__device__ __half g_Kh[ROWS*DM];
__device__ __half g_Vh[ROWS*DM];
__device__ __half g_VTh[ROWS*DM];             // V^T per batch [B][D][S]
__device__ float  g_Sc[(size_t)BB*SS*SS];     // fp32 scores (64 MB)
__device__ __half g_Ph[(size_t)BB*SS*SS];     // half probs (32 MB)
__device__ float  g_attn[ROWS*DM];
__device__ float  g_h[ROWS*DM];
__device__ __half g_hh[ROWS*DM];
__device__ __half g_f[ROWS*DF];               // FFN hidden, half
__device__ float  g_f2[ROWS*DM];
__device__ __half g_WqT[DM*DM];
__device__ __half g_WkT[DM*DM];
__device__ __half g_WvT[DM*DM];
__device__ __half g_W1T[(size_t)DF*DM];
__device__ __half g_W2T[(size_t)DM*DF];

// ---------------- helpers ----------------
__device__ __forceinline__ uint32_t smem_u32(const void* p) {
    return (uint32_t)__cvta_generic_to_shared(p);
}
__device__ __forceinline__ void cp_async16(void* dst, const void* src) {
    asm volatile("cp.async.cg.shared.global [%0], [%1], 16;"
                 :: "r"(smem_u32(dst)), "l"(src));
}
__device__ __forceinline__ void cp_commit() {
    asm volatile("cp.async.commit_group;");
}
__device__ __forceinline__ void cp_wait1() {
    asm volatile("cp.async.wait_group 1;");
}

__device__ __forceinline__ void ldsm_x4(uint32_t& r0, uint32_t& r1,
                                        uint32_t& r2, uint32_t& r3, uint32_t addr) {
    asm volatile("ldmatrix.sync.aligned.m8n8.x4.shared.b16 {%0,%1,%2,%3}, [%4];"
                 : "=r"(r0), "=r"(r1), "=r"(r2), "=r"(r3) : "r"(addr));
}

__device__ __forceinline__ void mma_f16(float c[4],
                                        uint32_t a0, uint32_t a1, uint32_t a2, uint32_t a3,
                                        uint32_t b0, uint32_t b1) {
    asm volatile(
        "mma.sync.aligned.m16n8k16.row.col.f32.f16.f16.f32 "
        "{%0,%1,%2,%3}, {%4,%5,%6,%7}, {%8,%9}, {%0,%1,%2,%3};"
        : "+f"(c[0]), "+f"(c[1]), "+f"(c[2]), "+f"(c[3])
        : "r"(a0), "r"(a1), "r"(a2), "r"(a3), "r"(b0), "r"(b1));
}

// ---------------- fp16 tensor-core GEMM NT ----------------
// C = alpha*(A[M,K] @ Bt[N,K]^T + bias); A,Bt half K-major; C float or half.
// M%128==0, N%128==0, K%64==0. Batched via blockIdx.z + strides.
template<int HASBIAS, int RELU, int OUTH>
__global__ void __launch_bounds__(256, 2)
gemm_h(const __half* __restrict__ A, const __half* __restrict__ Bt,
       const float* __restrict__ bias, void* __restrict__ Cv,
       int M, int N, int K, size_t sA, size_t sB, size_t sC, float alpha)
{
    extern __shared__ __half hsm[];

    const __half* Ab = A  + (size_t)blockIdx.z * sA;
    const __half* Bb = Bt + (size_t)blockIdx.z * sB;

    const int tid = threadIdx.x;
    const int wid = tid >> 5, lane = tid & 31;
    const int g   = lane >> 2, t4 = lane & 3;
    const int wm  = wid >> 2, wn = wid & 3;        // 2 x 4 warp grid, warp tile 64x32
    const int m0  = blockIdx.y * BM;
    const int n0  = blockIdx.x * BN;

    // ldmatrix per-lane row/col offsets (within a 16x16 A block / 16x16 B block)
    const int arow = lane & 15;            // lanes 0-15: rows 0-15
    const int acol = (lane >> 4) << 3;     // lanes 16-31: +8 cols
    const int brow = (lane & 7) + ((lane >> 4) << 3);   // m2,m3 -> rows 8-15
    const int bcol = ((lane >> 3) & 1) << 3;            // m1,m3 -> +8 cols

    float c[4][4][4] = {};

    auto aBase = [&](int s) { return hsm + s * STG_H; };
    auto bBase = [&](int s) { return hsm + s * STG_H + ASTG_H; };

    auto loadA = [&](int s, int k0) {
        __half* base = aBase(s);
        #pragma unroll
        for (int i = 0; i < 4; i++) {
            int ch = tid + i * 256;                // 1024 chunks: 128 rows x 8 x 16B
            int r = ch >> 3, cc = ch & 7;
            cp_async16(base + r * RP + cc * 8,
                       Ab + (size_t)(m0 + r) * K + k0 + cc * 8);
        }
    };
    auto loadB = [&](int s, int k0) {
        __half* base = bBase(s);
        #pragma unroll
        for (int i = 0; i < 4; i++) {
            int ch = tid + i * 256;
            int r = ch >> 3, cc = ch & 7;
            cp_async16(base + r * RP + cc * 8,
                       Bb + (size_t)(n0 + r) * K + k0 + cc * 8);
        }
    };

    const int T = K / BKH;

    loadA(0, 0);   loadB(0, 0);   cp_commit();
    loadA(1, BKH); loadB(1, BKH); cp_commit();

    for (int t = 0; t < T; t++) {
        cp_wait1();
        __syncthreads();
        int tn = t + 2;
        if (tn < T) { loadA(tn % NSTAGE, tn * BKH); loadB(tn % NSTAGE, tn * BKH); }
        cp_commit();

        const int p = t % NSTAGE;
        const uint32_t As0 = smem_u32(aBase(p));
        const uint32_t Bs0 = smem_u32(bBase(p));

        #pragma unroll
        for (int ks = 0; ks < 4; ks++) {
            const int kh = ks * 16;
            uint32_t a[4][4], b[4][2];
            #pragma unroll
            for (int mt = 0; mt < 4; mt++) {
                uint32_t addr = As0 + ((wm * 64 + mt * 16 + arow) * RP + kh + acol) * 2;
                ldsm_x4(a[mt][0], a[mt][1], a[mt][2], a[mt][3], addr);
            }
            #pragma unroll
            for (int np = 0; np < 2; np++) {
                uint32_t addr = Bs0 + ((wn * 32 + np * 16 + brow) * RP + kh + bcol) * 2;
                ldsm_x4(b[2*np][0], b[2*np][1], b[2*np+1][0], b[2*np+1][1], addr);
            }
            #pragma unroll
            for (int mt = 0; mt < 4; mt++)
                #pragma unroll
                for (int nt = 0; nt < 4; nt++)
                    mma_f16(c[mt][nt], a[mt][0], a[mt][1], a[mt][2], a[mt][3],
                            b[nt][0], b[nt][1]);
        }
    }

    // epilogue
    #pragma unroll
    for (int mt = 0; mt < 4; mt++) {
        #pragma unroll
        for (int nt = 0; nt < 4; nt++) {
            const int col = n0 + wn * 32 + nt * 8 + 2 * t4;
            float b0 = 0.f, b1 = 0.f;
            if (HASBIAS) { b0 = bias[col]; b1 = bias[col + 1]; }
            #pragma unroll
            for (int h = 0; h < 2; h++) {
                const int row = m0 + wm * 64 + mt * 16 + g + h * 8;
                float v0 = (c[mt][nt][2 * h + 0] + b0) * alpha;
                float v1 = (c[mt][nt][2 * h + 1] + b1) * alpha;
                if (RELU) { v0 = fmaxf(v0, 0.f); v1 = fmaxf(v1, 0.f); }
                if (OUTH) {
                    __half* Cb = (__half*)Cv + (size_t)blockIdx.z * sC;
                    *(__half2*)&Cb[(size_t)row * N + col] = __floats2half2_rn(v0, v1);
                } else {
                    float* Cb = (float*)Cv + (size_t)blockIdx.z * sC;
                    *(float2*)&Cb[(size_t)row * N + col] = make_float2(v0, v1);
                }
            }
        }
    }
}

// ---------------- convert fp32 -> fp16 (elementwise, float4) ----------------
__global__ void f2h_kernel(const float* __restrict__ in, __half* __restrict__ out)
{
    const int i = (blockIdx.x * blockDim.x + threadIdx.x) * 4;
    float4 v = *(const float4*)(in + i);
    *(__half2*)(out + i)     = __floats2half2_rn(v.x, v.y);
    *(__half2*)(out + i + 2) = __floats2half2_rn(v.z, v.w);
}

// ---------------- transpose + convert: in fp32 [R][C] -> out half [C][R] ----------------
__global__ void transpose_f2h(const float* __restrict__ in, __half* __restrict__ out,
                              int R, int C)
{
    __shared__ float tile[32][33];
    const int r0 = blockIdx.x * 32;
    const int c0 = blockIdx.y * 32;
    const int tx = threadIdx.x, ty = threadIdx.y;    // 32 x 8
    #pragma unroll
    for (int i = 0; i < 4; i++)
        tile[ty + i * 8][tx] = in[(size_t)(r0 + ty + i * 8) * C + c0 + tx];
    __syncthreads();
    #pragma unroll
    for (int i = 0; i < 4; i++)
        out[(size_t)(c0 + ty + i * 8) * R + r0 + tx] = __float2half_rn(tile[tx][ty + i * 8]);
}

// ---------------- transpose half, per-batch: in [b][R][C] -> out [b][C][R] ----------------
__global__ void transpose_h(const __half* __restrict__ in, __half* __restrict__ out,
                            int R, int C, size_t sIn, size_t sOut)
{
    __shared__ __half tile[32][34];
    const __half* ib = in  + (size_t)blockIdx.z * sIn;
    __half*       ob = out + (size_t)blockIdx.z * sOut;
    const int r0 = blockIdx.x * 32;
    const int c0 = blockIdx.y * 32;
    const int tx = threadIdx.x, ty = threadIdx.y;
    #pragma unroll
    for (int i = 0; i < 4; i++)
        tile[ty + i * 8][tx] = ib[(size_t)(r0 + ty + i * 8) * C + c0 + tx];
    __syncthreads();
    #pragma unroll
    for (int i = 0; i < 4; i++)
        ob[(size_t)(c0 + ty + i * 8) * R + r0 + tx] = tile[tx][ty + i * 8];
}

// ---------------- block reductions ----------------
__device__ __forceinline__ float blockAllReduceSum(float v) {
    __shared__ float sh[33];
    #pragma unroll
    for (int o = 16; o; o >>= 1) v += __shfl_xor_sync(0xffffffffu, v, o);
    int w = threadIdx.x >> 5;
    if ((threadIdx.x & 31) == 0) sh[w] = v;
    __syncthreads();
    if (threadIdx.x == 0) {
        float t = 0.f;
        int nw = blockDim.x >> 5;
        for (int i = 0; i < nw; i++) t += sh[i];
        sh[32] = t;
    }
    __syncthreads();
    float r = sh[32];
    __syncthreads();
    return r;
}

__device__ __forceinline__ float blockAllReduceMax(float v) {
    __shared__ float sh[33];
    #pragma unroll
    for (int o = 16; o; o >>= 1) v = fmaxf(v, __shfl_xor_sync(0xffffffffu, v, o));
    int w = threadIdx.x >> 5;
    if ((threadIdx.x & 31) == 0) sh[w] = v;
    __syncthreads();
    if (threadIdx.x == 0) {
        float t = -3.4e38f;
        int nw = blockDim.x >> 5;
        for (int i = 0; i < nw; i++) t = fmaxf(t, sh[i]);
        sh[32] = t;
    }
    __syncthreads();
    float r = sh[32];
    __syncthreads();
    return r;
}

// ---------------- row softmax: fp32 scores -> half probs, cols = 2048 ----------------
__global__ void softmax_kernel(const float* __restrict__ Sp, __half* __restrict__ Pp)
{
    const float4* row = (const float4*)(Sp + (size_t)blockIdx.x * SS);
    __half* orow = Pp + (size_t)blockIdx.x * SS;
    const int tid = threadIdx.x;

    float4 v[2];
    v[0] = row[tid];
    v[1] = row[tid + 256];

    float m = -3.4e38f;
    #pragma unroll
    for (int i = 0; i < 2; i++)
        m = fmaxf(m, fmaxf(fmaxf(v[i].x, v[i].y), fmaxf(v[i].z, v[i].w)));
    m = blockAllReduceMax(m);

    float s = 0.f;
    #pragma unroll
    for (int i = 0; i < 2; i++) {
        v[i].x = __expf(v[i].x - m); v[i].y = __expf(v[i].y - m);
        v[i].z = __expf(v[i].z - m); v[i].w = __expf(v[i].w - m);
        s += v[i].x + v[i].y + v[i].z + v[i].w;
    }
    s = blockAllReduceSum(s);
    float inv = 1.f / s;

    #pragma unroll
    for (int i = 0; i < 2; i++) {
        int base = (i == 0 ? tid : tid + 256) * 4;
        *(__half2*)(orow + base)     = __floats2half2_rn(v[i].x * inv, v[i].y * inv);
        *(__half2*)(orow + base + 2) = __floats2half2_rn(v[i].z * inv, v[i].w * inv);
    }
}

// ---------------- fused residual add + LayerNorm (+ optional half copy) ----------------
template<int WRITEH>
__global__ void add_ln_kernel(const float* __restrict__ a, const float* __restrict__ b,
                              const float* __restrict__ gamma, const float* __restrict__ beta,
                              float* __restrict__ out, __half* __restrict__ outh)
{
    const size_t row = blockIdx.x;
    const int tid = threadIdx.x;
    const float* ar = a + row * DM;
    const float* br = b + row * DM;

    float v0 = ar[tid]       + br[tid];
    float v1 = ar[tid + 256] + br[tid + 256];

    float s  = blockAllReduceSum(v0 + v1);
    float sq = blockAllReduceSum(v0 * v0 + v1 * v1);

    float mean = s * (1.f / DM);
    float var  = sq * (1.f / DM) - mean * mean;
    float inv  = rsqrtf(var + 1e-5f);

    float o0 = (v0 - mean) * inv * gamma[tid]       + beta[tid];
    float o1 = (v1 - mean) * inv * gamma[tid + 256] + beta[tid + 256];

    float* o = out + row * DM;
    o[tid]       = o0;
    o[tid + 256] = o1;
    if (WRITEH) {
        __half* oh = outh + row * DM;
        oh[tid]       = __float2half_rn(o0);
        oh[tid + 256] = __float2half_rn(o1);
    }
}

// ---------------- launch ----------------
extern "C" void kernel_launch(void* const* d_in, const int* in_sizes, int n_in,
                              void* d_out, int out_size)
{
    const float* q  = (const float*)d_in[0];
    const float* k  = (const float*)d_in[1];
    const float* v  = (const float*)d_in[2];
    const float* x  = (const float*)d_in[3];
    const float* Wq = (const float*)d_in[4];
    const float* bq = (const float*)d_in[5];
    const float* Wk = (const float*)d_in[6];
    const float* bk = (const float*)d_in[7];
    const float* Wv = (const float*)d_in[8];
    const float* bv = (const float*)d_in[9];
    const float* g1 = (const float*)d_in[10];
    const float* be1= (const float*)d_in[11];
    const float* W1 = (const float*)d_in[12];
    const float* b1 = (const float*)d_in[13];
    const float* W2 = (const float*)d_in[14];
    const float* b2 = (const float*)d_in[15];
    const float* g2 = (const float*)d_in[16];
    const float* be2= (const float*)d_in[17];
    float* out = (float*)d_out;

    __half *pqh, *pkh, *pvh, *pQh, *pKh, *pVh, *pVTh, *pPh, *phh, *pf;
    __half *pWqT, *pWkT, *pWvT, *pW1T, *pW2T;
    float *pS, *pAttn, *pH, *pF2;
    cudaGetSymbolAddress((void**)&pqh,  g_qh);
    cudaGetSymbolAddress((void**)&pkh,  g_kh);
    cudaGetSymbolAddress((void**)&pvh,  g_vh);
    cudaGetSymbolAddress((void**)&pQh,  g_Qh);
    cudaGetSymbolAddress((void**)&pKh,  g_Kh);
    cudaGetSymbolAddress((void**)&pVh,  g_Vh);
    cudaGetSymbolAddress((void**)&pVTh, g_VTh);
    cudaGetSymbolAddress((void**)&pS,   g_Sc);
    cudaGetSymbolAddress((void**)&pPh,  g_Ph);
    cudaGetSymbolAddress((void**)&pAttn,g_attn);
    cudaGetSymbolAddress((void**)&pH,   g_h);
    cudaGetSymbolAddress((void**)&phh,  g_hh);
    cudaGetSymbolAddress((void**)&pf,   g_f);
    cudaGetSymbolAddress((void**)&pF2,  g_f2);
    cudaGetSymbolAddress((void**)&pWqT, g_WqT);
    cudaGetSymbolAddress((void**)&pWkT, g_WkT);
    cudaGetSymbolAddress((void**)&pWvT, g_WvT);
    cudaGetSymbolAddress((void**)&pW1T, g_W1T);
    cudaGetSymbolAddress((void**)&pW2T, g_W2T);

    cudaFuncSetAttribute(gemm_h<1,0,1>, cudaFuncAttributeMaxDynamicSharedMemorySize, SMEM_H);
    cudaFuncSetAttribute(gemm_h<0,0,0>, cudaFuncAttributeMaxDynamicSharedMemorySize, SMEM_H);
    cudaFuncSetAttribute(gemm_h<1,1,1>, cudaFuncAttributeMaxDynamicSharedMemorySize, SMEM_H);
    cudaFuncSetAttribute(gemm_h<1,0,0>, cudaFuncAttributeMaxDynamicSharedMemorySize, SMEM_H);

    const float inv_sqrt_d = 1.f / sqrtf((float)DM);
    const dim3 t32x8(32, 8);

    // 0a) convert inputs to half
    f2h_kernel<<<ROWS * DM / 1024, 256>>>(q, pqh);
    f2h_kernel<<<ROWS * DM / 1024, 256>>>(k, pkh);
    f2h_kernel<<<ROWS * DM / 1024, 256>>>(v, pvh);

    // 0b) transpose + convert weights to half [N][K]
    transpose_f2h<<<dim3(DM/32, DM/32), t32x8>>>(Wq, pWqT, DM, DM);
    transpose_f2h<<<dim3(DM/32, DM/32), t32x8>>>(Wk, pWkT, DM, DM);
    transpose_f2h<<<dim3(DM/32, DM/32), t32x8>>>(Wv, pWvT, DM, DM);
    transpose_f2h<<<dim3(DM/32, DF/32), t32x8>>>(W1, pW1T, DM, DF);
    transpose_f2h<<<dim3(DF/32, DM/32), t32x8>>>(W2, pW2T, DF, DM);

    // 1) QKV projections -> half outputs (1/sqrt(d) folded into Q)
    {
        dim3 grid(DM / BN, ROWS / BM, 1);
        gemm_h<1,0,1><<<grid, 256, SMEM_H>>>(pqh, pWqT, bq, pQh, ROWS, DM, DM, 0, 0, 0, inv_sqrt_d);
        gemm_h<1,0,1><<<grid, 256, SMEM_H>>>(pkh, pWkT, bk, pKh, ROWS, DM, DM, 0, 0, 0, 1.f);
        gemm_h<1,0,1><<<grid, 256, SMEM_H>>>(pvh, pWvT, bv, pVh, ROWS, DM, DM, 0, 0, 0, 1.f);
    }

    // 2) V -> V^T per batch (half)
    transpose_h<<<dim3(SS/32, DM/32, BB), t32x8>>>(pVh, pVTh, SS, DM,
                                                   (size_t)SS*DM, (size_t)DM*SS);

    // 3) scores = Qs @ K^T -> fp32 (NT: B operand = K, K-major over D)
    {
        dim3 grid(SS / BN, SS / BM, BB);
        gemm_h<0,0,0><<<grid, 256, SMEM_H>>>(pQh, pKh, nullptr, pS, SS, SS, DM,
                                             (size_t)SS*DM, (size_t)SS*DM, (size_t)SS*SS, 1.f);
    }

    // 4) softmax fp32 -> half probs
    softmax_kernel<<<BB * SS, 256>>>(pS, pPh);

    // 5) attn = P @ V -> fp32 (NT with B = V^T [D,S])
    {
        dim3 grid(DM / BN, SS / BM, BB);
        gemm_h<0,0,0><<<grid, 256, SMEM_H>>>(pPh, pVTh, nullptr, pAttn, SS, DM, SS,
                                             (size_t)SS*SS, (size_t)DM*SS, (size_t)SS*DM, 1.f);
    }

    // 6) h = LN(attn + x), fp32 + half copy
    add_ln_kernel<1><<<ROWS, 256>>>(pAttn, x, g1, be1, pH, phh);

    // 7) f = relu(h @ W1 + b1) -> half
    {
        dim3 grid(DF / BN, ROWS / BM, 1);
        gemm_h<1,1,1><<<grid, 256, SMEM_H>>>(phh, pW1T, b1, pf, ROWS, DF, DM, 0, 0, 0, 1.f);
    }

    // 8) f2 = f @ W2 + b2 -> fp32
    {
        dim3 grid(DM / BN, ROWS / BM, 1);
        gemm_h<1,0,0><<<grid, 256, SMEM_H>>>(pf, pW2T, b2, pF2, ROWS, DM, DF, 0, 0, 0, 1.f);
    }

    // 9) out = LN(f2 + h)
    add_ln_kernel<0><<<ROWS, 256>>>(pF2, pH, g2, be2, out, nullptr);
}